// round 11
// baseline (speedup 1.0000x reference)
#include <cuda_runtime.h>
#include <cuda_bf16.h>
#include <cstdint>

// ---------------- Problem constants ----------------
#define N_ROWS   2048
#define DIM      256
#define T_TRK    256
#define NCOLS_XY 16384             // T*Q
#define BM       128
#define BN       128
#define NCT_XY   (NCOLS_XY / BN)   // 128
#define NCT_XX   (N_ROWS   / BN)   // 16
#define NCT_TOT  (NCT_XY + NCT_XX) // 144
#define KCHUNK   64                // bf16 per K chunk (128B rows, SW128)
#define NCHUNK   (DIM / KCHUNK)    // 4
#define NSTAGE   3
#define NCHNK_FIN 32               // finalize blocks (64 rows each)

// ---------------- Dynamic SMEM layout ----------------
#define A_STAGE  (BM * KCHUNK * 2)          // 16384
#define B_STAGE  (BN * KCHUNK * 2)          // 16384
#define OFF_A    0
#define OFF_B    (NSTAGE * A_STAGE)         // 49152
#define OFF_CTRK (OFF_B + NSTAGE * B_STAGE) // 98304
#define OFF_RTID (OFF_CTRK + BN * 4)        // 98816
#define OFF_REDT (OFF_RTID + BM * 4)        // 99328
#define OFF_REDP (OFF_REDT + BM * 2 * 4)    // 100352
#define SMEM_BYTES (OFF_REDP + BM * 2 * 4)  // 101376 (~99KB, 2 CTAs/SM)

// ---------------- Device scratch ----------------
static __device__ __nv_bfloat16 g_xb[N_ROWS * DIM];
static __device__ __nv_bfloat16 g_yb[NCOLS_XY * DIM];
static __device__ float g_tot[NCT_TOT * N_ROWS];
static __device__ float g_pos[NCT_TOT * N_ROWS];
static __device__ float g_diag[N_ROWS];
static __device__ float g_pnum[NCHNK_FIN * T_TRK];   // [chunk][track] coalesced
static __device__ float g_pden[NCHNK_FIN * T_TRK];
static __device__ int   g_pcnt[NCHNK_FIN * T_TRK];
static __device__ int   g_tick;

// ---------------- PTX helpers (baseline sm_80+, legal on plain sm_103) ----
__device__ __forceinline__ uint32_t smem_u32(const void* p) {
    uint32_t a;
    asm("{ .reg .u64 t; cvta.to.shared.u64 t, %1; cvt.u32.u64 %0, t; }" : "=r"(a) : "l"(p));
    return a;
}
__device__ __forceinline__ void cp_async16(uint32_t dst, const void* src) {
    asm volatile("cp.async.cg.shared.global [%0], [%1], 16;" :: "r"(dst), "l"(src));
}
#define CP_COMMIT() asm volatile("cp.async.commit_group;" ::: "memory")
#define CP_WAIT(n)  asm volatile("cp.async.wait_group %0;" :: "n"(n) : "memory")

__device__ __forceinline__ void ldsm4(uint32_t r[4], uint32_t addr) {
    asm volatile("ldmatrix.sync.aligned.m8n8.x4.shared.b16 {%0,%1,%2,%3}, [%4];"
                 : "=r"(r[0]), "=r"(r[1]), "=r"(r[2]), "=r"(r[3]) : "r"(addr));
}
__device__ __forceinline__ void mma16816(float c[4], const uint32_t a[4], const uint32_t b[2]) {
    asm volatile(
        "mma.sync.aligned.m16n8k16.row.col.f32.bf16.bf16.f32 "
        "{%0,%1,%2,%3}, {%4,%5,%6,%7}, {%8,%9}, {%0,%1,%2,%3};"
        : "+f"(c[0]), "+f"(c[1]), "+f"(c[2]), "+f"(c[3])
        : "r"(a[0]), "r"(a[1]), "r"(a[2]), "r"(a[3]), "r"(b[0]), "r"(b[1]));
}

// ---------------- fp32 -> bf16 conversions (split: x small, y large) ---------
#define NX4 (N_ROWS * DIM / 4)      // 131072
#define NY4 (NCOLS_XY * DIM / 4)    // 1048576
__global__ void conv_x(const float* __restrict__ x)
{
    int i = blockIdx.x * blockDim.x + threadIdx.x;      // 65536 threads, 2 f4 each
    if (i == 0) g_tick = 0;                             // reset finalize ticket
    #pragma unroll
    for (int h = 0; h < 2; h++) {
        int j = i + h * (NX4 / 2);
        float4 v = reinterpret_cast<const float4*>(x)[j];
        __nv_bfloat162* o = reinterpret_cast<__nv_bfloat162*>(g_xb);
        o[j * 2 + 0] = __floats2bfloat162_rn(v.x, v.y);
        o[j * 2 + 1] = __floats2bfloat162_rn(v.z, v.w);
    }
}
__global__ void conv_y(const float* __restrict__ y)
{
    int i = blockIdx.x * blockDim.x + threadIdx.x;      // 524288 threads, 2 f4 each
    #pragma unroll
    for (int h = 0; h < 2; h++) {
        int j = i + h * (NY4 / 2);
        float4 v = reinterpret_cast<const float4*>(y)[j];
        __nv_bfloat162* o = reinterpret_cast<__nv_bfloat162*>(g_yb);
        o[j * 2 + 0] = __floats2bfloat162_rn(v.x, v.y);
        o[j * 2 + 1] = __floats2bfloat162_rn(v.z, v.w);
    }
}

// ---------------- Fused HMMA GEMM + exp + row reductions ----------------
// ct = blockIdx.y + ctBase; ct < 128 -> xy tiles, >= 128 -> xx tiles.
// 128x128 tile, 256 threads, 2 CTAs/SM, K=64 chunks, 3-stage pipeline.
__global__ __launch_bounds__(256, 2)
void gemm_mma(const int* __restrict__ trk, int ctBase)
{
    extern __shared__ char smem[];
    const uint32_t sA = smem_u32(smem) + OFF_A;
    const uint32_t sB = smem_u32(smem) + OFF_B;
    int*   colTrkS = (int*)(smem + OFF_CTRK);
    int*   rowTidS = (int*)(smem + OFF_RTID);
    float* redT    = (float*)(smem + OFF_REDT);
    float* redP    = (float*)(smem + OFF_REDP);

    const int tid = threadIdx.x;
    const int wid = tid >> 5;
    const int lid = tid & 31;
    const int wm = wid & 3;      // warp m: rows wm*32..+31
    const int wn = wid >> 2;     // warp n: cols wn*64..+63

    const int bx = blockIdx.x;
    const int ct = blockIdx.y + ctBase;
    const bool isXX = (ct >= NCT_XY);
    const int rowBase = bx * BM;
    const int colBase = isXX ? (ct - NCT_XY) * BN : ct * BN;
    const __nv_bfloat16* Bsrc = isXX ? g_xb : g_yb;
    const bool diagBlk = isXX && (colBase == rowBase);

    if (tid < BN) colTrkS[tid] = isXX ? trk[colBase + tid] : ((colBase + tid) & (T_TRK - 1));
    if (tid < BM) rowTidS[tid] = trk[rowBase + tid];

    // ---- ldmatrix base offsets at K-step 0 (SW128: c16 ^ (r&7)); step s: ^ (s<<5)
    uint32_t aOff0[2];
    #pragma unroll
    for (int mt = 0; mt < 2; mt++) {
        int r = wm * 32 + mt * 16 + (lid & 7) + ((lid >> 3) & 1) * 8;
        uint32_t c16 = (uint32_t)((lid >> 4) & 1);
        aOff0[mt] = (uint32_t)(r * 128) + ((c16 ^ (uint32_t)(r & 7)) * 16);
    }
    uint32_t bOff0[4];
    #pragma unroll
    for (int ntp = 0; ntp < 4; ntp++) {
        int r = wn * 64 + ntp * 16 + (lid & 7) + ((lid >> 4) & 1) * 8;
        uint32_t c16 = (uint32_t)((lid >> 3) & 1);
        bOff0[ntp] = (uint32_t)(r * 128) + ((c16 ^ (uint32_t)(r & 7)) * 16);
    }

    float c[2][8][4];
    #pragma unroll
    for (int mt = 0; mt < 2; mt++)
        #pragma unroll
        for (int nt = 0; nt < 8; nt++)
            #pragma unroll
            for (int k = 0; k < 4; k++) c[mt][nt][k] = 0.f;

    auto load_chunk = [&](int stage, int kc) {
        const int kEl = kc * KCHUNK;
        uint32_t dstA = sA + (uint32_t)stage * A_STAGE;
        uint32_t dstB = sB + (uint32_t)stage * B_STAGE;
        #pragma unroll
        for (int i = 0; i < 4; i++) {
            int idx = tid + i * 256;            // 0..1023
            int r = idx >> 3, c8 = idx & 7;
            uint32_t off = (uint32_t)(r * 128) + (((uint32_t)c8 ^ (uint32_t)(r & 7)) * 16);
            cp_async16(dstA + off, g_xb + (rowBase + r) * DIM + kEl + c8 * 8);
            cp_async16(dstB + off, Bsrc + (colBase + r) * DIM + kEl + c8 * 8);
        }
    };

    load_chunk(0, 0); CP_COMMIT();
    load_chunk(1, 1); CP_COMMIT();

    #pragma unroll
    for (int kc = 0; kc < NCHUNK; kc++) {
        if (kc == NCHUNK - 1) { CP_WAIT(0); } else { CP_WAIT(1); }  // chunk kc arrived
        __syncthreads();                       // orders compute(kc-1) before refill below
        if (kc + 2 < NCHUNK) {
            load_chunk((kc + 2) % NSTAGE, kc + 2);
            CP_COMMIT();
        }

        const uint32_t baseA = sA + (uint32_t)(kc % NSTAGE) * A_STAGE;
        const uint32_t baseB = sB + (uint32_t)(kc % NSTAGE) * B_STAGE;
        #pragma unroll
        for (int s = 0; s < 4; s++) {
            const uint32_t sx = (uint32_t)(s << 5);
            uint32_t a[2][4], b[4][4];
            ldsm4(a[0], baseA + (aOff0[0] ^ sx));
            ldsm4(a[1], baseA + (aOff0[1] ^ sx));
            #pragma unroll
            for (int ntp = 0; ntp < 4; ntp++) ldsm4(b[ntp], baseB + (bOff0[ntp] ^ sx));
            #pragma unroll
            for (int mt = 0; mt < 2; mt++)
                #pragma unroll
                for (int nt = 0; nt < 8; nt++)
                    mma16816(c[mt][nt], a[mt], &b[nt >> 1][(nt & 1) * 2]);
        }
    }

    // ---- epilogue: exp + track-matched row partials ----
    const float INV_TEMP = 1.0f / 0.3f;
    float tot[2][2] = {{0.f, 0.f}, {0.f, 0.f}};
    float pos[2][2] = {{0.f, 0.f}, {0.f, 0.f}};
    int rt[2][2];
    #pragma unroll
    for (int mt = 0; mt < 2; mt++)
        #pragma unroll
        for (int h = 0; h < 2; h++)
            rt[mt][h] = rowTidS[wm * 32 + mt * 16 + (lid >> 2) + 8 * h];

    #pragma unroll
    for (int nt = 0; nt < 8; nt++) {
        const int colL = wn * 64 + nt * 8 + 2 * (lid & 3);
        const int ct0 = colTrkS[colL], ct1 = colTrkS[colL + 1];
        #pragma unroll
        for (int mt = 0; mt < 2; mt++)
            #pragma unroll
            for (int h = 0; h < 2; h++) {
                float e0 = __expf(c[mt][nt][2 * h + 0] * INV_TEMP);
                float e1 = __expf(c[mt][nt][2 * h + 1] * INV_TEMP);
                tot[mt][h] += e0 + e1;
                if (ct0 == rt[mt][h]) pos[mt][h] += e0;
                if (ct1 == rt[mt][h]) pos[mt][h] += e1;
                if (diagBlk) {
                    int rowg = rowBase + wm * 32 + mt * 16 + (lid >> 2) + 8 * h;
                    int colg = colBase + colL;
                    if (colg == rowg) g_diag[rowg] = e0;
                    if (colg + 1 == rowg) g_diag[rowg] = e1;
                }
            }
    }

    #pragma unroll
    for (int mt = 0; mt < 2; mt++)
        #pragma unroll
        for (int h = 0; h < 2; h++) {
            tot[mt][h] += __shfl_xor_sync(0xffffffffu, tot[mt][h], 1);
            tot[mt][h] += __shfl_xor_sync(0xffffffffu, tot[mt][h], 2);
            pos[mt][h] += __shfl_xor_sync(0xffffffffu, pos[mt][h], 1);
            pos[mt][h] += __shfl_xor_sync(0xffffffffu, pos[mt][h], 2);
        }

    if ((lid & 3) == 0) {
        #pragma unroll
        for (int mt = 0; mt < 2; mt++)
            #pragma unroll
            for (int h = 0; h < 2; h++) {
                int r = wm * 32 + mt * 16 + (lid >> 2) + 8 * h;
                redT[r * 2 + wn] = tot[mt][h];
                redP[r * 2 + wn] = pos[mt][h];
            }
    }
    __syncthreads();

    if (tid < BM) {
        g_tot[ct * N_ROWS + rowBase + tid] = redT[tid * 2] + redT[tid * 2 + 1];
        g_pos[ct * N_ROWS + rowBase + tid] = redP[tid * 2] + redP[tid * 2 + 1];
    }
}

// ---------------- Fused finalize + last-block final reduce --------------------
__global__ __launch_bounds__(256)
void finalize_fused(const int* __restrict__ trk, float* __restrict__ out)
{
    __shared__ float sXT[4][64], sXP[4][64], sQT[4][64], sQP[4][64];
    __shared__ float sN[64], sD[64];
    __shared__ int   sT[64];
    __shared__ bool  isLast;

    const int r = threadIdx.x & 63;
    const int g = threadIdx.x >> 6;
    const int row = blockIdx.x * 64 + r;

    float xyT = 0.f, xyP = 0.f, xxT = 0.f, xxP = 0.f;
    #pragma unroll 4
    for (int c = g * 36; c < (g + 1) * 36; c++) {
        float t = g_tot[c * N_ROWS + row];
        float p = g_pos[c * N_ROWS + row];
        if (c < NCT_XY) { xyT += t; xyP += p; }
        else            { xxT += t; xxP += p; }
    }
    sXT[g][r] = xyT; sXP[g][r] = xyP; sQT[g][r] = xxT; sQP[g][r] = xxP;
    __syncthreads();

    if (g == 0) {
        float aT = sXT[0][r] + sXT[1][r] + sXT[2][r] + sXT[3][r];
        float aP = sXP[0][r] + sXP[1][r] + sXP[2][r] + sXP[3][r];
        float bT = sQT[0][r] + sQT[1][r] + sQT[2][r] + sQT[3][r];
        float bP = sQP[0][r] + sQP[1][r] + sQP[2][r] + sQP[3][r];
        float dg = g_diag[row];
        sN[r] = aP + 0.5f * (bP - dg);
        sD[r] = (aT - aP) + (bT - bP);
        sT[r] = trk[row];
    }
    __syncthreads();

    const int t = threadIdx.x;
    {
        float num = 0.f, den = 0.f; int cnt = 0;
        #pragma unroll 8
        for (int i = 0; i < 64; i++) {
            if (sT[i] == t) { num += sN[i]; den += sD[i]; cnt++; }
        }
        g_pnum[blockIdx.x * T_TRK + t] = num;
        g_pden[blockIdx.x * T_TRK + t] = den;
        g_pcnt[blockIdx.x * T_TRK + t] = cnt;
    }

    __threadfence();
    if (threadIdx.x == 0) isLast = (atomicAdd(&g_tick, 1) == NCHNK_FIN - 1);
    __syncthreads();
    if (!isLast) return;

    float num = 0.f, den = 0.f; int cnt = 0;
    #pragma unroll
    for (int j = 0; j < NCHNK_FIN; j++) {
        num += g_pnum[j * T_TRK + t];
        den += g_pden[j * T_TRK + t];
        cnt += g_pcnt[j * T_TRK + t];
    }
    float loss = 0.f; int pres = 0;
    if (cnt > 0) { pres = 1; loss = -logf(num / (den + num)); }

    __shared__ float sL[T_TRK];
    __shared__ int   sP[T_TRK];
    sL[t] = loss; sP[t] = pres;
    __syncthreads();
    for (int s = T_TRK / 2; s > 0; s >>= 1) {
        if (t < s) { sL[t] += sL[t + s]; sP[t] += sP[t + s]; }
        __syncthreads();
    }
    if (t == 0) out[0] = sL[0] / (float)sP[0];
}

extern "C" void kernel_launch(void* const* d_in, const int* in_sizes, int n_in,
                              void* d_out, int out_size)
{
    const float* x   = (const float*)d_in[0];   // [2048, 256]
    const int*   trk = (const int*)  d_in[1];   // [2048]
    const float* y   = (const float*)d_in[2];   // [256, 64, 256]
    float* out = (float*)d_out;

    // One-time resource init (first call = correctness run, outside capture).
    static cudaStream_t s2 = nullptr;
    static cudaEvent_t eFork = nullptr, eJoin = nullptr;
    if (s2 == nullptr) {
        cudaStreamCreateWithFlags(&s2, cudaStreamNonBlocking);
        cudaEventCreateWithFlags(&eFork, cudaEventDisableTiming);
        cudaEventCreateWithFlags(&eJoin, cudaEventDisableTiming);
        cudaFuncSetAttribute(gemm_mma, cudaFuncAttributeMaxDynamicSharedMemorySize, SMEM_BYTES);
    }

    // Fork: convert_y on s2 runs concurrently with convert_x + gemm_xx on s0.
    cudaEventRecord(eFork, 0);
    cudaStreamWaitEvent(s2, eFork, 0);
    conv_y<<<NY4 / 2 / 256, 256, 0, s2>>>(y);
    cudaEventRecord(eJoin, s2);

    conv_x<<<NX4 / 2 / 256, 256>>>(x);
    dim3 gridXX(N_ROWS / BM, NCT_XX);                    // (16, 16): needs g_xb only
    gemm_mma<<<gridXX, 256, SMEM_BYTES>>>(trk, NCT_XY);

    // Join: xy GEMM needs g_yb.
    cudaStreamWaitEvent(0, eJoin, 0);
    dim3 gridXY(N_ROWS / BM, NCT_XY);                    // (16, 128)
    gemm_mma<<<gridXY, 256, SMEM_BYTES>>>(trk, 0);

    finalize_fused<<<NCHNK_FIN, 256>>>(trk, out);
}

// round 12
// speedup vs baseline: 1.1061x; 1.1061x over previous
#include <cuda_runtime.h>
#include <cuda_bf16.h>
#include <cstdint>

// ---------------- Problem constants ----------------
#define N_ROWS   2048
#define DIM      256
#define T_TRK    256
#define NCOLS_XY 16384             // T*Q
#define BM       128
#define BN       128
#define NCT_XY   (NCOLS_XY / BN)   // 128
#define NCT_XX   (N_ROWS   / BN)   // 16
#define NCT_TOT  (NCT_XY + NCT_XX) // 144
#define KCHUNK   64                // bf16 per K chunk (128B rows, SW128)
#define NCHUNK   (DIM / KCHUNK)    // 4
#define NSTAGE   3
#define NCHNK_FIN 32               // finalize blocks (64 rows each)

// ---------------- Dynamic SMEM layout ----------------
#define A_STAGE  (BM * KCHUNK * 2)          // 16384
#define B_STAGE  (BN * KCHUNK * 2)          // 16384
#define OFF_A    0
#define OFF_B    (NSTAGE * A_STAGE)         // 49152
#define OFF_CTRK (OFF_B + NSTAGE * B_STAGE) // 98304
#define OFF_RTID (OFF_CTRK + BN * 4)        // 98816
#define OFF_REDT (OFF_RTID + BM * 4)        // 99328
#define OFF_REDP (OFF_REDT + BM * 2 * 4)    // 100352
#define SMEM_BYTES (OFF_REDP + BM * 2 * 4)  // 101376 (~99KB, 2 CTAs/SM)

// ---------------- Device scratch ----------------
static __device__ __nv_bfloat16 g_xb[N_ROWS * DIM];
static __device__ __nv_bfloat16 g_yb[NCOLS_XY * DIM];
static __device__ float g_tot[NCT_TOT * N_ROWS];
static __device__ float g_pos[NCT_TOT * N_ROWS];
static __device__ float g_diag[N_ROWS];
static __device__ float g_pnum[NCHNK_FIN * T_TRK];   // [chunk][track] coalesced
static __device__ float g_pden[NCHNK_FIN * T_TRK];
static __device__ int   g_pcnt[NCHNK_FIN * T_TRK];
static __device__ int   g_tick;

// ---------------- PTX helpers (baseline sm_80+, legal on plain sm_103) ----
__device__ __forceinline__ uint32_t smem_u32(const void* p) {
    uint32_t a;
    asm("{ .reg .u64 t; cvta.to.shared.u64 t, %1; cvt.u32.u64 %0, t; }" : "=r"(a) : "l"(p));
    return a;
}
__device__ __forceinline__ void cp_async16(uint32_t dst, const void* src) {
    asm volatile("cp.async.cg.shared.global [%0], [%1], 16;" :: "r"(dst), "l"(src));
}
#define CP_COMMIT() asm volatile("cp.async.commit_group;" ::: "memory")
#define CP_WAIT(n)  asm volatile("cp.async.wait_group %0;" :: "n"(n) : "memory")

__device__ __forceinline__ void ldsm4(uint32_t r[4], uint32_t addr) {
    asm volatile("ldmatrix.sync.aligned.m8n8.x4.shared.b16 {%0,%1,%2,%3}, [%4];"
                 : "=r"(r[0]), "=r"(r[1]), "=r"(r[2]), "=r"(r[3]) : "r"(addr));
}
__device__ __forceinline__ void mma16816(float c[4], const uint32_t a[4], const uint32_t b[2]) {
    asm volatile(
        "mma.sync.aligned.m16n8k16.row.col.f32.bf16.bf16.f32 "
        "{%0,%1,%2,%3}, {%4,%5,%6,%7}, {%8,%9}, {%0,%1,%2,%3};"
        : "+f"(c[0]), "+f"(c[1]), "+f"(c[2]), "+f"(c[3])
        : "r"(a[0]), "r"(a[1]), "r"(a[2]), "r"(a[3]), "r"(b[0]), "r"(b[1]));
}

// ---------------- fp32 -> bf16 conversion (x and y, 2 float4/thread) ---------
#define NX4 (N_ROWS * DIM / 4)      // 131072
#define NY4 (NCOLS_XY * DIM / 4)    // 1048576
#define NTOT4 (NX4 + NY4)           // 1179648
#define NHALF4 (NTOT4 / 2)          // 589824
__global__ void to_bf16_all(const float* __restrict__ x, const float* __restrict__ y)
{
    int i = blockIdx.x * blockDim.x + threadIdx.x;
    if (i == 0) g_tick = 0;                         // reset finalize ticket each call
    if (i >= NHALF4) return;
    #pragma unroll
    for (int h = 0; h < 2; h++) {
        int j = i + h * NHALF4;
        const float* s; __nv_bfloat16* d; int k;
        if (j < NX4) { s = x; d = g_xb; k = j; }
        else         { s = y; d = g_yb; k = j - NX4; }
        float4 v = reinterpret_cast<const float4*>(s)[k];
        __nv_bfloat162* o = reinterpret_cast<__nv_bfloat162*>(d);
        o[k * 2 + 0] = __floats2bfloat162_rn(v.x, v.y);
        o[k * 2 + 1] = __floats2bfloat162_rn(v.z, v.w);
    }
}

// ---------------- Fused HMMA GEMM + exp + row reductions ----------------
// grid (16, 144): blockIdx.y < 128 -> xy column tiles, >= 128 -> xx tiles.
// 128x128 tile, 256 threads, 2 CTAs/SM, K=64 chunks, 3-stage pipeline.
// PDL: prologue overlaps the conversion kernel's tail; grid-sync before
// first read of g_xb/g_yb.
__global__ __launch_bounds__(256, 2)
void gemm_mma(const int* __restrict__ trk)
{
    extern __shared__ char smem[];
    const uint32_t sA = smem_u32(smem) + OFF_A;
    const uint32_t sB = smem_u32(smem) + OFF_B;
    int*   colTrkS = (int*)(smem + OFF_CTRK);
    int*   rowTidS = (int*)(smem + OFF_RTID);
    float* redT    = (float*)(smem + OFF_REDT);
    float* redP    = (float*)(smem + OFF_REDP);

    const int tid = threadIdx.x;
    const int wid = tid >> 5;
    const int lid = tid & 31;
    const int wm = wid & 3;      // warp m: rows wm*32..+31
    const int wn = wid >> 2;     // warp n: cols wn*64..+63

    const int bx = blockIdx.x;
    const int ct = blockIdx.y;
    const bool isXX = (ct >= NCT_XY);
    const int rowBase = bx * BM;
    const int colBase = isXX ? (ct - NCT_XY) * BN : ct * BN;
    const __nv_bfloat16* Bsrc = isXX ? g_xb : g_yb;
    const bool diagBlk = isXX && (colBase == rowBase);

    if (tid < BN) colTrkS[tid] = isXX ? trk[colBase + tid] : ((colBase + tid) & (T_TRK - 1));
    if (tid < BM) rowTidS[tid] = trk[rowBase + tid];

    // ---- ldmatrix base offsets at K-step 0 (SW128: c16 ^ (r&7)); step s: ^ (s<<5)
    uint32_t aOff0[2];
    #pragma unroll
    for (int mt = 0; mt < 2; mt++) {
        int r = wm * 32 + mt * 16 + (lid & 7) + ((lid >> 3) & 1) * 8;
        uint32_t c16 = (uint32_t)((lid >> 4) & 1);
        aOff0[mt] = (uint32_t)(r * 128) + ((c16 ^ (uint32_t)(r & 7)) * 16);
    }
    uint32_t bOff0[4];
    #pragma unroll
    for (int ntp = 0; ntp < 4; ntp++) {
        int r = wn * 64 + ntp * 16 + (lid & 7) + ((lid >> 4) & 1) * 8;
        uint32_t c16 = (uint32_t)((lid >> 3) & 1);
        bOff0[ntp] = (uint32_t)(r * 128) + ((c16 ^ (uint32_t)(r & 7)) * 16);
    }

    float c[2][8][4];
    #pragma unroll
    for (int mt = 0; mt < 2; mt++)
        #pragma unroll
        for (int nt = 0; nt < 8; nt++)
            #pragma unroll
            for (int k = 0; k < 4; k++) c[mt][nt][k] = 0.f;

    auto load_chunk = [&](int stage, int kc) {
        const int kEl = kc * KCHUNK;
        uint32_t dstA = sA + (uint32_t)stage * A_STAGE;
        uint32_t dstB = sB + (uint32_t)stage * B_STAGE;
        #pragma unroll
        for (int i = 0; i < 4; i++) {
            int idx = tid + i * 256;            // 0..1023
            int r = idx >> 3, c8 = idx & 7;
            uint32_t off = (uint32_t)(r * 128) + (((uint32_t)c8 ^ (uint32_t)(r & 7)) * 16);
            cp_async16(dstA + off, g_xb + (rowBase + r) * DIM + kEl + c8 * 8);
            cp_async16(dstB + off, Bsrc + (colBase + r) * DIM + kEl + c8 * 8);
        }
    };

    // PDL: wait for the conversion kernel before consuming g_xb/g_yb.
    cudaGridDependencySynchronize();

    load_chunk(0, 0); CP_COMMIT();
    load_chunk(1, 1); CP_COMMIT();

    #pragma unroll
    for (int kc = 0; kc < NCHUNK; kc++) {
        if (kc == NCHUNK - 1) { CP_WAIT(0); } else { CP_WAIT(1); }  // chunk kc arrived
        __syncthreads();                       // orders compute(kc-1) before refill below
        if (kc + 2 < NCHUNK) {
            load_chunk((kc + 2) % NSTAGE, kc + 2);
            CP_COMMIT();
        }

        const uint32_t baseA = sA + (uint32_t)(kc % NSTAGE) * A_STAGE;
        const uint32_t baseB = sB + (uint32_t)(kc % NSTAGE) * B_STAGE;
        #pragma unroll
        for (int s = 0; s < 4; s++) {
            const uint32_t sx = (uint32_t)(s << 5);
            uint32_t a[2][4], b[4][4];
            ldsm4(a[0], baseA + (aOff0[0] ^ sx));
            ldsm4(a[1], baseA + (aOff0[1] ^ sx));
            #pragma unroll
            for (int ntp = 0; ntp < 4; ntp++) ldsm4(b[ntp], baseB + (bOff0[ntp] ^ sx));
            #pragma unroll
            for (int mt = 0; mt < 2; mt++)
                #pragma unroll
                for (int nt = 0; nt < 8; nt++)
                    mma16816(c[mt][nt], a[mt], &b[nt >> 1][(nt & 1) * 2]);
        }
    }

    // ---- epilogue: exp + track-matched row partials ----
    const float INV_TEMP = 1.0f / 0.3f;
    float tot[2][2] = {{0.f, 0.f}, {0.f, 0.f}};
    float pos[2][2] = {{0.f, 0.f}, {0.f, 0.f}};
    int rt[2][2];
    #pragma unroll
    for (int mt = 0; mt < 2; mt++)
        #pragma unroll
        for (int h = 0; h < 2; h++)
            rt[mt][h] = rowTidS[wm * 32 + mt * 16 + (lid >> 2) + 8 * h];

    #pragma unroll
    for (int nt = 0; nt < 8; nt++) {
        const int colL = wn * 64 + nt * 8 + 2 * (lid & 3);
        const int ct0 = colTrkS[colL], ct1 = colTrkS[colL + 1];
        #pragma unroll
        for (int mt = 0; mt < 2; mt++)
            #pragma unroll
            for (int h = 0; h < 2; h++) {
                float e0 = __expf(c[mt][nt][2 * h + 0] * INV_TEMP);
                float e1 = __expf(c[mt][nt][2 * h + 1] * INV_TEMP);
                tot[mt][h] += e0 + e1;
                if (ct0 == rt[mt][h]) pos[mt][h] += e0;
                if (ct1 == rt[mt][h]) pos[mt][h] += e1;
                if (diagBlk) {
                    int rowg = rowBase + wm * 32 + mt * 16 + (lid >> 2) + 8 * h;
                    int colg = colBase + colL;
                    if (colg == rowg) g_diag[rowg] = e0;
                    if (colg + 1 == rowg) g_diag[rowg] = e1;
                }
            }
    }

    #pragma unroll
    for (int mt = 0; mt < 2; mt++)
        #pragma unroll
        for (int h = 0; h < 2; h++) {
            tot[mt][h] += __shfl_xor_sync(0xffffffffu, tot[mt][h], 1);
            tot[mt][h] += __shfl_xor_sync(0xffffffffu, tot[mt][h], 2);
            pos[mt][h] += __shfl_xor_sync(0xffffffffu, pos[mt][h], 1);
            pos[mt][h] += __shfl_xor_sync(0xffffffffu, pos[mt][h], 2);
        }

    if ((lid & 3) == 0) {
        #pragma unroll
        for (int mt = 0; mt < 2; mt++)
            #pragma unroll
            for (int h = 0; h < 2; h++) {
                int r = wm * 32 + mt * 16 + (lid >> 2) + 8 * h;
                redT[r * 2 + wn] = tot[mt][h];
                redP[r * 2 + wn] = pos[mt][h];
            }
    }
    __syncthreads();

    if (tid < BM) {
        g_tot[ct * N_ROWS + rowBase + tid] = redT[tid * 2] + redT[tid * 2 + 1];
        g_pos[ct * N_ROWS + rowBase + tid] = redP[tid * 2] + redP[tid * 2 + 1];
    }
}

// ---------------- Fused finalize + last-block final reduce --------------------
__global__ __launch_bounds__(256)
void finalize_fused(const int* __restrict__ trk, float* __restrict__ out)
{
    __shared__ float sXT[4][64], sXP[4][64], sQT[4][64], sQP[4][64];
    __shared__ float sN[64], sD[64];
    __shared__ int   sT[64];
    __shared__ bool  isLast;

    const int r = threadIdx.x & 63;
    const int g = threadIdx.x >> 6;
    const int row = blockIdx.x * 64 + r;

    // PDL: wait for gemm before consuming g_tot/g_pos/g_diag.
    cudaGridDependencySynchronize();

    float xyT = 0.f, xyP = 0.f, xxT = 0.f, xxP = 0.f;
    #pragma unroll 4
    for (int c = g * 36; c < (g + 1) * 36; c++) {
        float t = g_tot[c * N_ROWS + row];
        float p = g_pos[c * N_ROWS + row];
        if (c < NCT_XY) { xyT += t; xyP += p; }
        else            { xxT += t; xxP += p; }
    }
    sXT[g][r] = xyT; sXP[g][r] = xyP; sQT[g][r] = xxT; sQP[g][r] = xxP;
    __syncthreads();

    if (g == 0) {
        float aT = sXT[0][r] + sXT[1][r] + sXT[2][r] + sXT[3][r];
        float aP = sXP[0][r] + sXP[1][r] + sXP[2][r] + sXP[3][r];
        float bT = sQT[0][r] + sQT[1][r] + sQT[2][r] + sQT[3][r];
        float bP = sQP[0][r] + sQP[1][r] + sQP[2][r] + sQP[3][r];
        float dg = g_diag[row];
        sN[r] = aP + 0.5f * (bP - dg);
        sD[r] = (aT - aP) + (bT - bP);
        sT[r] = trk[row];
    }
    __syncthreads();

    const int t = threadIdx.x;
    {
        float num = 0.f, den = 0.f; int cnt = 0;
        #pragma unroll 8
        for (int i = 0; i < 64; i++) {
            if (sT[i] == t) { num += sN[i]; den += sD[i]; cnt++; }
        }
        g_pnum[blockIdx.x * T_TRK + t] = num;
        g_pden[blockIdx.x * T_TRK + t] = den;
        g_pcnt[blockIdx.x * T_TRK + t] = cnt;
    }

    __threadfence();
    if (threadIdx.x == 0) isLast = (atomicAdd(&g_tick, 1) == NCHNK_FIN - 1);
    __syncthreads();
    if (!isLast) return;

    float num = 0.f, den = 0.f; int cnt = 0;
    #pragma unroll
    for (int j = 0; j < NCHNK_FIN; j++) {
        num += g_pnum[j * T_TRK + t];
        den += g_pden[j * T_TRK + t];
        cnt += g_pcnt[j * T_TRK + t];
    }
    float loss = 0.f; int pres = 0;
    if (cnt > 0) { pres = 1; loss = -logf(num / (den + num)); }

    __shared__ float sL[T_TRK];
    __shared__ int   sP[T_TRK];
    sL[t] = loss; sP[t] = pres;
    __syncthreads();
    for (int s = T_TRK / 2; s > 0; s >>= 1) {
        if (t < s) { sL[t] += sL[t + s]; sP[t] += sP[t + s]; }
        __syncthreads();
    }
    if (t == 0) out[0] = sL[0] / (float)sP[0];
}

extern "C" void kernel_launch(void* const* d_in, const int* in_sizes, int n_in,
                              void* d_out, int out_size)
{
    const float* x   = (const float*)d_in[0];   // [2048, 256]
    const int*   trk = (const int*)  d_in[1];   // [2048]
    const float* y   = (const float*)d_in[2];   // [256, 64, 256]
    float* out = (float*)d_out;

    static bool init_done = false;
    if (!init_done) {
        cudaFuncSetAttribute(gemm_mma, cudaFuncAttributeMaxDynamicSharedMemorySize, SMEM_BYTES);
        init_done = true;
    }

    to_bf16_all<<<(NHALF4 + 255) / 256, 256>>>(x, y);

    // gemm with programmatic dependent launch (prologue overlaps conversion tail)
    {
        cudaLaunchConfig_t cfg = {};
        cfg.gridDim = dim3(N_ROWS / BM, NCT_TOT);   // (16, 144)
        cfg.blockDim = dim3(256);
        cfg.dynamicSmemBytes = SMEM_BYTES;
        cfg.stream = 0;
        cudaLaunchAttribute attr[1];
        attr[0].id = cudaLaunchAttributeProgrammaticStreamSerialization;
        attr[0].val.programmaticStreamSerializationAllowed = 1;
        cfg.attrs = attr;
        cfg.numAttrs = 1;
        cudaLaunchKernelEx(&cfg, gemm_mma, trk);
    }

    // finalize with PDL (prologue overlaps gemm tail)
    {
        cudaLaunchConfig_t cfg = {};
        cfg.gridDim = dim3(NCHNK_FIN);
        cfg.blockDim = dim3(256);
        cfg.dynamicSmemBytes = 0;
        cfg.stream = 0;
        cudaLaunchAttribute attr[1];
        attr[0].id = cudaLaunchAttributeProgrammaticStreamSerialization;
        attr[0].val.programmaticStreamSerializationAllowed = 1;
        cfg.attrs = attr;
        cfg.numAttrs = 1;
        cudaLaunchKernelEx(&cfg, finalize_fused, trk, out);
    }
}